// round 9
// baseline (speedup 1.0000x reference)
#include <cuda_runtime.h>
#include <cuda_bf16.h>
#include <math.h>

// Problem constants
#define BB 32
#define SS 1024
#define EE 512
#define HH 256
#define G4 1024          // 4*H

// ---------------- static scratch (no allocations) ----------------
__device__ float    g_xg[(size_t)2 * SS * G4 * BB];     // [d][t][g][b]
__device__ float    g_WT[(size_t)2 * EE * G4];          // [d][e][g]
__device__ int      g_tok[2 * SS * BB];                 // [d][t*32+b]
__device__ int      g_j[2 * SS * BB];                   // [d][t*32+b] out row or -1
__device__ float    g_hprev[2][2][HH * BB];             // [d][buf][k*32+b]
__device__ unsigned g_cnt[2];

__device__ __forceinline__ float sigm(float x) { return 1.0f / (1.0f + __expf(-x)); }

__device__ __forceinline__ void fma2(unsigned long long &d,
                                     unsigned long long a, unsigned long long b) {
    asm("fma.rn.f32x2 %0, %1, %2, %0;" : "+l"(d) : "l"(a), "l"(b));
}
__device__ __forceinline__ unsigned long long add2(unsigned long long a,
                                                   unsigned long long b) {
    unsigned long long r;
    asm("add.rn.f32x2 %0, %1, %2;" : "=l"(r) : "l"(a), "l"(b));
    return r;
}
__device__ __forceinline__ unsigned long long dup2(float x) {
    unsigned long long r; asm("mov.b64 %0, {%1, %1};" : "=l"(r) : "f"(x)); return r;
}
__device__ __forceinline__ float2 unpk(unsigned long long v) {
    float2 r; asm("mov.b64 {%0, %1}, %2;" : "=f"(r.x), "=f"(r.y) : "l"(v)); return r;
}

// ---------------- prep: inverse permutation, token arrays, state reset --------
__global__ __launch_bounds__(1024) void k_prep(const int* __restrict__ inputs,
                                               const int* __restrict__ seqlen,
                                               const int* __restrict__ fmask)
{
    int b = blockIdx.x;
    int t = threadIdx.x;
    __shared__ int sc[SS];
    int m = (fmask[b * SS + t] != 0) ? 1 : 0;
    sc[t] = m;
    __syncthreads();
    for (int off = 1; off < SS; off <<= 1) {
        int v = (t >= off) ? sc[t - off] : 0;
        __syncthreads();
        sc[t] += v;
        __syncthreads();
    }
    int r   = sc[t];          // inclusive rank
    int cnt = sc[SS - 1];
    g_j[t * BB + b]           = m ? (r - 1)   : -1;   // fwd out row
    g_j[SS * BB + t * BB + b] = m ? (cnt - r) : -1;   // bwd out row

    int len = seqlen[b];
    g_tok[t * BB + b] = inputs[b * SS + t];
    g_tok[SS * BB + t * BB + b] = (t < len) ? inputs[b * SS + (len - 1 - t)] : 0;

    if (b == 0) {
        for (int i = t; i < 2 * HH * BB; i += 1024) {
            int d = i / (HH * BB);
            g_hprev[d][0][i - d * HH * BB] = 0.0f;
        }
        if (t < 2) g_cnt[t] = 0u;
    }
}

// ---------------- tiled transpose W_ih[g][e] -> WT[e][g] -----------------------
__global__ __launch_bounds__(256) void k_wt(const float* __restrict__ fW,
                                            const float* __restrict__ bW)
{
    __shared__ float tile[32][33];
    int d  = blockIdx.z;
    int g0 = blockIdx.x * 32;
    int e0 = blockIdx.y * 32;
    const float* W = d ? bW : fW;
    int tx = threadIdx.x & 31, ty = threadIdx.x >> 5;  // 32 x 8
#pragma unroll
    for (int j = 0; j < 4; j++) {
        int g = g0 + ty + j * 8;
        tile[ty + j * 8][tx] = W[(size_t)g * EE + e0 + tx];
    }
    __syncthreads();
#pragma unroll
    for (int j = 0; j < 4; j++) {
        int e = e0 + ty + j * 8;
        g_WT[(size_t)d * EE * G4 + (size_t)e * G4 + g0 + tx] = tile[tx][ty + j * 8];
    }
}

// ---------------- xg GEMM: 128x128 tile, 8x8 micro, f32x2, fused gather --------
__global__ __launch_bounds__(256) void k_gemm(
    const float* __restrict__ emb,
    const float* __restrict__ fbih, const float* __restrict__ fbhh,
    const float* __restrict__ bbih, const float* __restrict__ bbhh)
{
    const int d  = blockIdx.z;
    const int g0 = blockIdx.y * 128;
    const int n0 = blockIdx.x * 128;
    const float* __restrict__ WT  = g_WT + (size_t)d * EE * G4;
    const int*   __restrict__ tok = g_tok + d * SS * BB;
    const float* __restrict__ bih = d ? bbih : fbih;
    const float* __restrict__ bhh = d ? bbhh : fbhh;

    __shared__ __align__(16) float As[16 * 128];      // [k][m]
    __shared__ __align__(16) float Bs[16 * 132];      // [k][n] padded
    __shared__ int ts[128];

    const int tid = threadIdx.x;
    if (tid < 128) ts[tid] = tok[n0 + tid];
    __syncthreads();

    const int ty = tid >> 4;      // m octet
    const int tx = tid & 15;      // n octet

    const int akr = tid >> 5;            // k row (and +8)
    const int am4 = (tid & 31) * 4;
    const int bn  = tid >> 2;            // n (and +64)
    const int bk4 = (tid & 3) * 4;
    const size_t arow0 = (size_t)akr * G4 + g0 + am4;
    const size_t arow1 = (size_t)(akr + 8) * G4 + g0 + am4;
    const size_t brow0 = (size_t)ts[bn] * EE + bk4;
    const size_t brow1 = (size_t)ts[bn + 64] * EE + bk4;

    unsigned long long acc[8][4] = {};

    float4 pa0 = *(const float4*)(WT + arow0);
    float4 pa1 = *(const float4*)(WT + arow1);
    float4 pb0 = *(const float4*)(emb + brow0);
    float4 pb1 = *(const float4*)(emb + brow1);

    for (int kt = 0; kt < 32; kt++) {
        *(float4*)&As[akr * 128 + am4]       = pa0;
        *(float4*)&As[(akr + 8) * 128 + am4] = pa1;
        Bs[(bk4 + 0) * 132 + bn] = pb0.x;  Bs[(bk4 + 1) * 132 + bn] = pb0.y;
        Bs[(bk4 + 2) * 132 + bn] = pb0.z;  Bs[(bk4 + 3) * 132 + bn] = pb0.w;
        Bs[(bk4 + 0) * 132 + bn + 64] = pb1.x;  Bs[(bk4 + 1) * 132 + bn + 64] = pb1.y;
        Bs[(bk4 + 2) * 132 + bn + 64] = pb1.z;  Bs[(bk4 + 3) * 132 + bn + 64] = pb1.w;
        __syncthreads();

        if (kt < 31) {
            int k0 = (kt + 1) * 16;
            pa0 = *(const float4*)(WT + (size_t)k0 * G4 + arow0);
            pa1 = *(const float4*)(WT + (size_t)k0 * G4 + arow1);
            pb0 = *(const float4*)(emb + brow0 + k0);
            pb1 = *(const float4*)(emb + brow1 + k0);
        }

#pragma unroll
        for (int k = 0; k < 16; k++) {
            float4 af0 = *(float4*)&As[k * 128 + ty * 8];
            float4 af1 = *(float4*)&As[k * 128 + ty * 8 + 4];
            ulonglong2 bq0 = *(ulonglong2*)&Bs[k * 132 + tx * 8];
            ulonglong2 bq1 = *(ulonglong2*)&Bs[k * 132 + tx * 8 + 4];
            unsigned long long ad[8];
            ad[0] = dup2(af0.x); ad[1] = dup2(af0.y);
            ad[2] = dup2(af0.z); ad[3] = dup2(af0.w);
            ad[4] = dup2(af1.x); ad[5] = dup2(af1.y);
            ad[6] = dup2(af1.z); ad[7] = dup2(af1.w);
#pragma unroll
            for (int i = 0; i < 8; i++) {
                fma2(acc[i][0], ad[i], bq0.x);
                fma2(acc[i][1], ad[i], bq0.y);
                fma2(acc[i][2], ad[i], bq1.x);
                fma2(acc[i][3], ad[i], bq1.y);
            }
        }
        __syncthreads();
    }

    int nb = n0 + tx * 8;
    int t  = nb >> 5;
    int b0 = nb & 31;
    size_t base_d = (size_t)d * SS * G4 * BB;
#pragma unroll
    for (int i = 0; i < 8; i++) {
        int grow = g0 + ty * 8 + i;
        float bias = bih[grow] + bhh[grow];
        float2 p0 = unpk(acc[i][0]);
        float2 p1 = unpk(acc[i][1]);
        float2 p2 = unpk(acc[i][2]);
        float2 p3 = unpk(acc[i][3]);
        size_t off = base_d + (((size_t)t * G4 + grow) << 5) + b0;
        *(float4*)&g_xg[off]     = make_float4(p0.x + bias, p0.y + bias, p1.x + bias, p1.y + bias);
        *(float4*)&g_xg[off + 4] = make_float4(p2.x + bias, p2.y + bias, p3.x + bias, p3.y + bias);
    }
}

// ---------------- persistent recurrence: direct-LDG h, fused reduce+nonlin ----
// 128 blocks: d = bx>>6, blk = bx&63. Block owns hidden units 4*blk..4*blk+3
// (16 gate rows). Warp s loads only its own k-slice of h via ld.global.cg.
__global__ __launch_bounds__(256) void k_rec(const float* __restrict__ fWhh,
                                             const float* __restrict__ bWhh,
                                             float* __restrict__ out, int rows)
{
    __shared__ __align__(16) float4 wp4[4][256];            // 16KB
    __shared__ __align__(16) unsigned long long ps[2048];   // 16KB [(s*8+j)*32+lane]
    __shared__ float hstage[128];                           // [b*4+u]

    const int d   = blockIdx.x >> 6;
    const int blk = blockIdx.x & 63;
    const float* __restrict__ Whh = d ? bWhh : fWhh;

    const int tid  = threadIdx.x;
    const int s    = tid >> 5;      // warp id = k chunk
    const int lane = tid & 31;      // batch

    for (int idx = tid; idx < 1024; idx += 256) {
        int rg = idx >> 8, k = idx & 255;
        int gb4 = blk * 4 + rg;
        wp4[rg][k] = make_float4(Whh[(size_t)(0 * HH + gb4) * HH + k],
                                 Whh[(size_t)(1 * HH + gb4) * HH + k],
                                 Whh[(size_t)(2 * HH + gb4) * HH + k],
                                 Whh[(size_t)(3 * HH + gb4) * HH + k]);
    }

    const float* __restrict__ xgd = g_xg + (size_t)d * SS * G4 * BB;
    const int*   __restrict__ jd_arr = g_j + d * SS * BB;
    unsigned* cnt = &g_cnt[d];

    const int u  = s & 3;           // reduce/nonlin unit (warps 0-3)
    const int ck = blk * 4 + u;
    float c = 0.0f;

    // per-thread xg addresses (4 gates of unit ck, batch=lane)
    size_t xoff0 = ((size_t)(0 * HH + ck) << 5) + lane;
    size_t xoff1 = ((size_t)(1 * HH + ck) << 5) + lane;
    size_t xoff2 = ((size_t)(2 * HH + ck) << 5) + lane;
    size_t xoff3 = ((size_t)(3 * HH + ck) << 5) + lane;

    float xi = 0, xf = 0, xgg = 0, xo = 0;
    if (tid < 128) {
        xi  = xgd[xoff0];
        xf  = xgd[xoff1];
        xgg = xgd[xoff2];
        xo  = xgd[xoff3];
    }
    int jreg = (tid < 32) ? jd_arr[tid] : -1;

    const int kbase = s * 32;
    const size_t outbase = (size_t)d * 256 + blk * 4;
    __syncthreads();   // wp4 ready

    for (int t = 0; t < SS; t++) {
        const float* rbuf = g_hprev[d][t & 1];
        float*       wbuf = g_hprev[d][(t + 1) & 1];

        // load this warp's k-slice of h(t-1) directly (L2, bypass L1)
        float hv[32];
#pragma unroll
        for (int kk = 0; kk < 32; kk++)
            hv[kk] = __ldcg(rbuf + ((kbase + kk) << 5) + lane);

        unsigned long long a0 = 0, a1 = 0, a2 = 0, a3 = 0,
                           a4 = 0, a5 = 0, a6 = 0, a7 = 0;
#pragma unroll
        for (int kk = 0; kk < 32; kk++) {
            int k = kbase + kk;
            unsigned long long hd = dup2(hv[kk]);
            ulonglong2 w01 = *(const ulonglong2*)&wp4[0][k];
            ulonglong2 w23 = *(const ulonglong2*)&wp4[1][k];
            ulonglong2 w45 = *(const ulonglong2*)&wp4[2][k];
            ulonglong2 w67 = *(const ulonglong2*)&wp4[3][k];
            fma2(a0, w01.x, hd); fma2(a1, w01.y, hd);
            fma2(a2, w23.x, hd); fma2(a3, w23.y, hd);
            fma2(a4, w45.x, hd); fma2(a5, w45.y, hd);
            fma2(a6, w67.x, hd); fma2(a7, w67.y, hd);
        }
        {
            unsigned long long* p = &ps[(s * 8) * 32 + lane];
            p[0 * 32] = a0; p[1 * 32] = a1; p[2 * 32] = a2; p[3 * 32] = a3;
            p[4 * 32] = a4; p[5 * 32] = a5; p[6 * 32] = a6; p[7 * 32] = a7;
        }
        __syncthreads();                                  // S2: psum ready

        if (tid < 128) {
            // fused reduce + nonlinearity for (unit u, batch lane)
            unsigned long long sif = 0, sgo = 0;
#pragma unroll
            for (int s2 = 0; s2 < 8; s2++) {
                sif = add2(sif, ps[(s2 * 8 + 2 * u) * 32 + lane]);
                sgo = add2(sgo, ps[(s2 * 8 + 2 * u + 1) * 32 + lane]);
            }
            float2 pif = unpk(sif);
            float2 pgo = unpk(sgo);
            float gi = pif.x + xi;
            float gf = pif.y + xf;
            float gg = pgo.x + xgg;
            float go = pgo.y + xo;
            c = sigm(gf) * c + sigm(gi) * tanhf(gg);
            float h = sigm(go) * tanhf(c);
            wbuf[(ck << 5) + lane] = h;
            hstage[lane * 4 + u] = h;
            // prefetch next step's xg
            int tn = (t + 1 < SS) ? (t + 1) : t;
            size_t xb = (size_t)tn * (G4 * BB);
            xi  = xgd[xb + xoff0];
            xf  = xgd[xb + xoff1];
            xgg = xgd[xb + xoff2];
            xo  = xgd[xb + xoff3];
        }
        __syncthreads();                                  // S3: h/hstage visible

        if (tid < 32) {
            int jo = jreg;
            if (jo >= 0 && jo < rows) {
                float4 hvv = *(float4*)&hstage[tid * 4];
                *(float4*)(out + ((size_t)tid * rows + jo) * 512 + outbase) = hvv;
            }
            int tn = (t + 1 < SS) ? (t + 1) : t;
            jreg = jd_arr[tn * BB + tid];
        } else if (tid == 224) {
            asm volatile("red.release.gpu.add.u32 [%0], %1;" :: "l"(cnt), "r"(1u) : "memory");
            unsigned target = 64u * (unsigned)(t + 1);
            unsigned v;
            do {
                asm volatile("ld.acquire.gpu.u32 %0, [%1];" : "=r"(v) : "l"(cnt) : "memory");
            } while (v < target);
        }
        __syncthreads();                                  // S4: barrier done
    }
}

// ---------------- launch ------------------------------------------------------
extern "C" void kernel_launch(void* const* d_in, const int* in_sizes, int n_in,
                              void* d_out, int out_size)
{
    const int*   inputs = (const int*)d_in[0];
    const int*   seqlen = (const int*)d_in[1];
    const int*   fmask  = (const int*)d_in[2];
    // d_in[3] = bmask (unused by the reference math)
    int base = (in_sizes[4] == 1) ? 5 : 4;   // skip out_seq_length scalar if present
    const float* emb   = (const float*)d_in[base + 0];
    const float* f_Wih = (const float*)d_in[base + 1];
    const float* f_Whh = (const float*)d_in[base + 2];
    const float* f_bih = (const float*)d_in[base + 3];
    const float* f_bhh = (const float*)d_in[base + 4];
    const float* b_Wih = (const float*)d_in[base + 5];
    const float* b_Whh = (const float*)d_in[base + 6];
    const float* b_bih = (const float*)d_in[base + 7];
    const float* b_bhh = (const float*)d_in[base + 8];
    (void)n_in;

    int rows = out_size / (BB * 512);        // out_seq_length

    cudaMemsetAsync(d_out, 0, (size_t)out_size * sizeof(float), 0);
    k_prep<<<BB, SS>>>(inputs, seqlen, fmask);
    k_wt<<<dim3(32, 16, 2), 256>>>(f_Wih, b_Wih);
    k_gemm<<<dim3(256, 8, 2), 256>>>(emb, f_bih, f_bhh, b_bih, b_bhh);
    k_rec<<<128, 256>>>(f_Whh, b_Whh, (float*)d_out, rows);
}